// round 17
// baseline (speedup 1.0000x reference)
#include <cuda_runtime.h>
#include <cuda_fp16.h>
#include <stdint.h>
#include <cstdint>
#include <math.h>

#define B_ 2
#define S_ 1024
#define D_ 2048
#define H_ 16
#define G_ 4
#define DH_ 128
#define NQ_ 2048
#define NKV_ 512
#define NTOT_ 3072
#define MROWS_ 2048
#define PZ_ (2048*3072)
#define BHS_ (B_*H_*S_)

// GEMMs: single fp16, KC=64, pitch 128 swizzled, 3 stages
#define KC 64
#define TILE_GB 16384
#define STAGE_GB (2 * TILE_GB)
#define GEMM_SMEM (3 * STAGE_GB + 512)

// Attention (all single fp16, 3 P regions)
#define QT 128
#define KT 64
#define QTILE 32768
#define KTILE 16384
#define VTILE 16384
#define PTILE 16384
#define K_OFF 32768
#define V_OFF 65536
#define P_OFF 98304
#define ATT_SMEM 147456

#define SCALE0 0.17677669529663687f
#define SCALE1 0.125f
#define SCALE2 0.08838834764831843f

// ---------------- device scratch ----------------
__device__ float g_part[2*2048*3072];
__device__ float g_lsum[2*3*BHS_];
__device__ __half g_x [MROWS_*D_];
__device__ __half g_Wt[NTOT_*D_];
__device__ __half g_Wot[D_*D_];
__device__ __half g_AO[MROWS_*D_];
__device__ __half g_Q [B_*H_*S_*DH_];
__device__ __half g_K [B_*G_*S_*DH_];
__device__ __half g_Vt[B_*G_*DH_*S_];

// ---------------- matryoshka reorder ----------------
__device__ __forceinline__ int perm16(int h, int d) {
    return (d < 32) ? (h*32 + d)
         : (d < 64) ? (512 + h*32 + (d-32))
                    : (1024 + h*64 + (d-64));
}
__device__ __forceinline__ int perm4(int g, int d) {
    return (d < 32) ? (g*32 + d)
         : (d < 64) ? (128 + g*32 + (d-32))
                    : (256 + g*64 + (d-64));
}

// ---------------- PTX helpers ----------------
__device__ __forceinline__ uint32_t smem_u32(const void* p) {
    uint32_t a;
    asm("{ .reg .u64 t; cvta.to.shared.u64 t, %1; cvt.u32.u64 %0, t; }" : "=r"(a) : "l"(p));
    return a;
}
__device__ __forceinline__ void cp_async16(uint32_t d, const void* g) {
    asm volatile("cp.async.cg.shared.global [%0], [%1], 16;" :: "r"(d), "l"(g));
}
__device__ __forceinline__ void ldsm4(uint32_t* r, uint32_t addr) {
    asm volatile("ldmatrix.sync.aligned.m8n8.x4.shared.b16 {%0,%1,%2,%3}, [%4];"
                 : "=r"(r[0]), "=r"(r[1]), "=r"(r[2]), "=r"(r[3]) : "r"(addr));
}
__device__ __forceinline__ void mma16816(float* c, const uint32_t* a, const uint32_t* b) {
    asm volatile(
        "mma.sync.aligned.m16n8k16.row.col.f32.f16.f16.f32 "
        "{%0,%1,%2,%3}, {%4,%5,%6,%7}, {%8,%9}, {%0,%1,%2,%3};"
        : "+f"(c[0]), "+f"(c[1]), "+f"(c[2]), "+f"(c[3])
        : "r"(a[0]), "r"(a[1]), "r"(a[2]), "r"(a[3]), "r"(b[0]), "r"(b[1]));
}
__device__ __forceinline__ void bar_pair(int id) {
    asm volatile("bar.sync %0, 64;" :: "r"(id) : "memory");
}
__device__ __forceinline__ uint32_t swz128(int r, int c) { return (uint32_t)r*128 + (uint32_t)((c ^ (r&7)) << 4); }
__device__ __forceinline__ uint32_t swz256(int r, int c) { return (uint32_t)r*256 + (uint32_t)((c ^ (r&7)) << 4); }

// ================= merged converter =================
// z=0: x -> fp16 (8192 blocks of 256 float4)
// z=1: W_qkv^T perm fold (48 x 32 tiles)
// z=2: Wo^T row-perm fold (32 x 32 tiles)
__global__ __launch_bounds__(256)
void conv_all_kernel(const float* __restrict__ x,
                     const float* __restrict__ Wq, const float* __restrict__ Wk,
                     const float* __restrict__ Wv, const float* __restrict__ Wo)
{
    const int tid = threadIdx.x;
    if (blockIdx.z == 0) {
        if (blockIdx.y != 0) return;
        int i = blockIdx.x * 256 + tid;
        if (i >= MROWS_*D_/4) return;
        float4 v = reinterpret_cast<const float4*>(x)[i];
        __half2* p = reinterpret_cast<__half2*>(g_x);
        p[2*i]   = __half2(__float2half(v.x), __float2half(v.y));
        p[2*i+1] = __half2(__float2half(v.z), __float2half(v.w));
        return;
    }
    __shared__ float ts[64][65];
    const int n0 = blockIdx.x * 64, k0 = blockIdx.y * 64;
    if (blockIdx.z == 1) {
        if (blockIdx.x >= NTOT_/64 || blockIdx.y >= D_/64) return;
        for (int idx = tid; idx < 4096; idx += 256) {
            int kk = idx >> 6, nn = idx & 63;
            int n = n0 + nn;
            const float* W; int ldw, src;
            if (n < NQ_)            { W = Wq; ldw = NQ_;  src = perm16(n >> 7, n & 127); }
            else if (n < NQ_+NKV_)  { int t = n - NQ_;        W = Wk; ldw = NKV_; src = perm4(t >> 7, t & 127); }
            else                    { int t = n - NQ_ - NKV_; W = Wv; ldw = NKV_; src = perm4(t >> 7, t & 127); }
            ts[kk][nn] = W[(size_t)(k0 + kk) * ldw + src];
        }
        __syncthreads();
        for (int idx = tid; idx < 4096; idx += 256) {
            int nn = idx >> 6, kk = idx & 63;
            g_Wt[(size_t)(n0 + nn) * D_ + k0 + kk] = __float2half(ts[kk][nn]);
        }
    } else {
        if (blockIdx.x >= D_/64 || blockIdx.y >= D_/64) return;
        for (int idx = tid; idx < 4096; idx += 256) {
            int kk = idx >> 6, nn = idx & 63;
            int k = k0 + kk;
            int srcrow = perm16(k >> 7, k & 127);
            ts[kk][nn] = Wo[(size_t)srcrow * D_ + n0 + nn];
        }
        __syncthreads();
        for (int idx = tid; idx < 4096; idx += 256) {
            int nn = idx >> 6, kk = idx & 63;
            g_Wot[(size_t)(n0 + nn) * D_ + k0 + kk] = __float2half(ts[kk][nn]);
        }
    }
}

// ================= fp16 single-product GEMM, KC=64 =================
template<int MODE>
__global__ __launch_bounds__(256, 2)
void gemm_mma_kernel(const __half* __restrict__ As, const __half* __restrict__ Bs,
                     float* __restrict__ outp,
                     const float* __restrict__ bq, const float* __restrict__ bk,
                     const float* __restrict__ bv)
{
    extern __shared__ char smem[];
    const uint32_t sb = smem_u32(smem);
    float* sBias = reinterpret_cast<float*>(smem + 3 * STAGE_GB);

    const int tid  = threadIdx.x;
    const int lane = tid & 31;
    const int wid  = tid >> 5;
    const int wm = wid >> 1;
    const int wn = wid & 1;
    const int n0 = blockIdx.x * 128;
    const int m0 = blockIdx.y * 128;
    const int NK = D_ / KC;   // 32

    if (tid < 128) {
        int n = n0 + tid;
        float b;
        if (MODE == 0) {
            if (n < NQ_)            b = bq[perm16(n >> 7, n & 127)];
            else if (n < NQ_+NKV_)  { int t = n - NQ_;        b = bk[perm4(t >> 7, t & 127)]; }
            else                    { int t = n - NQ_ - NKV_; b = bv[perm4(t >> 7, t & 127)]; }
        } else b = bq[n];
        sBias[tid] = b;
    }

    const __half* srcs[2] = { As + (size_t)m0 * D_, Bs + (size_t)n0 * D_ };

    auto load_stage = [&](int chunk) {
        const uint32_t st = sb + (uint32_t)(chunk % 3) * STAGE_GB;
        const int k0 = chunk * KC;
        #pragma unroll
        for (int t = 0; t < 2; t++) {
            const __half* s = srcs[t];
            const uint32_t tb = st + t * TILE_GB;
            #pragma unroll
            for (int it = 0; it < 4; it++) {
                int idx = tid + it * 256;
                int r = idx >> 3, c = idx & 7;
                cp_async16(tb + swz128(r, c), s + (size_t)r * D_ + k0 + c * 8);
            }
        }
        asm volatile("cp.async.commit_group;" ::: "memory");
    };

    float acc[2][8][4];
    #pragma unroll
    for (int mi = 0; mi < 2; mi++)
        #pragma unroll
        for (int ni = 0; ni < 8; ni++)
            #pragma unroll
            for (int q = 0; q < 4; q++) acc[mi][ni][q] = 0.f;

    const int mat = lane >> 3, rin = lane & 7;
    const int arow = wm*32 + (mat & 1)*8 + rin;
    const int acb  = (mat >> 1);
    const int brow = wn*64 + (mat >> 1)*8 + rin;
    const int bcb  = (mat & 1);

    load_stage(0);
    load_stage(1);

    for (int i = 0; i < NK; i++) {
        if (i >= NK - 1) asm volatile("cp.async.wait_group 0;" ::: "memory");
        else             asm volatile("cp.async.wait_group 1;" ::: "memory");
        __syncthreads();
        if (i + 2 < NK) load_stage(i + 2);

        const uint32_t st = sb + (uint32_t)(i % 3) * STAGE_GB;
        const uint32_t aA = st, bB = st + TILE_GB;

        #pragma unroll
        for (int kk = 0; kk < 4; kk++) {
            uint32_t af[2][4];
            #pragma unroll
            for (int mi = 0; mi < 2; mi++) {
                int r = arow + mi*16;
                ldsm4(af[mi], aA + swz128(r, kk*2 + acb));
            }
            uint32_t bf[8][2];
            #pragma unroll
            for (int nb2 = 0; nb2 < 4; nb2++) {
                int r = brow + nb2*16;
                uint32_t r4[4];
                ldsm4(r4, bB + swz128(r, kk*2 + bcb));
                bf[2*nb2][0] = r4[0]; bf[2*nb2][1] = r4[1];
                bf[2*nb2+1][0] = r4[2]; bf[2*nb2+1][1] = r4[3];
            }
            #pragma unroll
            for (int mi = 0; mi < 2; mi++)
                #pragma unroll
                for (int ni = 0; ni < 8; ni++)
                    mma16816(acc[mi][ni], af[mi], bf[ni]);
        }
    }

    // ---------- epilogue ----------
    const int g = lane >> 2, tig = lane & 3;
    #pragma unroll
    for (int mi = 0; mi < 2; mi++)
        #pragma unroll
        for (int ni = 0; ni < 8; ni++) {
            int col = wn*64 + ni*8 + tig*2;
            float b0 = sBias[col], b1 = sBias[col + 1];
            #pragma unroll
            for (int half = 0; half < 2; half++) {
                int row = m0 + wm*32 + mi*16 + g + half*8;
                float vx = acc[mi][ni][half*2+0] + b0;
                float vy = acc[mi][ni][half*2+1] + b1;
                if (MODE == 0) {
                    int bb = row >> 10, s = row & 1023;
                    __half2 hv = __half2(__float2half(vx), __float2half(vy));
                    if (n0 < NQ_) {
                        int h = n0 >> 7;
                        size_t o = ((size_t)((bb*H_ + h)*S_ + s))*DH_ + col;
                        *reinterpret_cast<__half2*>(g_Q + o) = hv;
                    } else if (n0 < NQ_+NKV_) {
                        int gg = (n0 - NQ_) >> 7;
                        size_t o = ((size_t)((bb*G_ + gg)*S_ + s))*DH_ + col;
                        *reinterpret_cast<__half2*>(g_K + o) = hv;
                    } else {
                        int gg = (n0 - NQ_ - NKV_) >> 7;
                        size_t o = ((size_t)(bb*G_ + gg)*DH_ + col)*S_ + s;
                        g_Vt[o]      = __float2half(vx);
                        g_Vt[o + S_] = __float2half(vy);
                    }
                } else {
                    *reinterpret_cast<float2*>(outp + (size_t)row * D_ + n0 + col) =
                        make_float2(vx, vy);
                }
            }
        }
}

// ================= fp16 flash attention, split-KV x2, fused 3-level PV =================
__global__ __launch_bounds__(512, 1)
void attn_mma_kernel()
{
    extern __shared__ char smem[];
    const uint32_t sb = smem_u32(smem);
    const int tid = threadIdx.x, lane = tid & 31, wid = tid >> 5;
    const int qt2 = (S_/QT - 1) - blockIdx.x;
    const int h = blockIdx.y;
    const int zz = blockIdx.z & 1, b = blockIdx.z >> 1;
    const int g = h >> 2;
    const int q0 = qt2 * QT;
    const int ktS = zz * (qt2 + 1);
    const int ktE = ktS + qt2 + 1;
    const int wq = (wid >> 1) * 16;
    const int wk = wid & 1;
    const int barid = 1 + (wid >> 1);
    const int mat = lane >> 3, rin = lane & 7;
    const int gq = lane >> 2, tig = lane & 3;

    const __half* Kp = g_K  + ((size_t)(b*G_ + g) * S_) * DH_;
    const __half* Vp = g_Vt + (size_t)(b*G_ + g) * DH_ * S_;
    const __half* Qp = g_Q  + ((size_t)(b*H_ + h) * S_ + q0) * DH_;

    auto issue_KV = [&](int kt) {
        const uint32_t kst = sb + K_OFF + (uint32_t)(kt & 1) * KTILE;
        const uint32_t vst = sb + V_OFF + (uint32_t)(kt & 1) * VTILE;
        const int k0 = kt * KT;
        #pragma unroll
        for (int i = 0; i < 2; i++) {
            int idx = tid + i * 512;
            { int r = idx >> 4, c = idx & 15;
              cp_async16(kst + swz256(r, c), Kp + (size_t)(k0 + r)*DH_ + c*8); }
            { int r = idx >> 3, c = idx & 7;
              cp_async16(vst + swz128(r, c), Vp + (size_t)r*S_ + k0 + c*8); }
        }
        asm volatile("cp.async.commit_group;" ::: "memory");
    };

    #pragma unroll
    for (int i = 0; i < 4; i++) {
        int idx = tid + i * 512; int r = idx >> 4, c = idx & 15;
        cp_async16(sb + swz256(r, c), Qp + (size_t)r*DH_ + c*8);
    }
    issue_KV(ktS);

    float o0[2][4] = {}, o1[2][4] = {}, o2[4][4] = {};
    float lsum[3][2] = {};

    const int rq = wq + (mat & 1)*8 + rin;
    const uint32_t qrow_off = (uint32_t)rq * 256;
    const int qsw = rq & 7;
    const uint32_t prow_off = (uint32_t)rq * 128;
    char* pwp = smem + P_OFF;
    float* lred = reinterpret_cast<float*>(smem + P_OFF);

    for (int kt = ktS; kt < ktE; kt++) {
        asm volatile("cp.async.wait_group 0;" ::: "memory");
        __syncthreads();
        if (kt + 1 < ktE) issue_KV(kt + 1);

        const int k0 = kt * KT;
        const uint32_t kst = sb + K_OFF + (uint32_t)(kt & 1) * KTILE;
        const uint32_t vst = sb + V_OFF + (uint32_t)(kt & 1) * VTILE;

        float acc[4][4];
        #pragma unroll
        for (int nb = 0; nb < 4; nb++)
            #pragma unroll
            for (int q = 0; q < 4; q++) acc[nb][q] = 0.f;

        auto qk_steps = [&](int kkA, int kkB) {
            #pragma unroll
            for (int kk = kkA; kk < kkB; kk++) {
                uint32_t qh[4];
                uint32_t qoff = qrow_off + (uint32_t)(((kk*2 + (mat>>1)) ^ qsw) << 4);
                ldsm4(qh, sb + qoff);
                uint32_t bh[4][2];
                #pragma unroll
                for (int nb2 = 0; nb2 < 2; nb2++) {
                    int rk = wk*32 + nb2*16 + (mat >> 1)*8 + rin;
                    uint32_t off = swz256(rk, kk*2 + (mat & 1));
                    uint32_t r4[4];
                    ldsm4(r4, kst + off);
                    bh[2*nb2][0] = r4[0]; bh[2*nb2][1] = r4[1];
                    bh[2*nb2+1][0] = r4[2]; bh[2*nb2+1][1] = r4[3];
                }
                #pragma unroll
                for (int nb = 0; nb < 4; nb++) mma16816(acc[nb], qh, bh[nb]);
            }
        };

        auto do_exp = [&](float scale, float* ls, int L) {
            const int r0g = q0 + wq + gq, r1g = r0g + 8;
            const bool need_mask = (k0 + wk*32 + 31 > q0 + wq);
            char* pL = pwp + L * PTILE;
            #pragma unroll
            for (int nb = 0; nb < 4; nb++) {
                int colg = k0 + wk*32 + nb*8 + tig*2;
                float p0 = __expf(acc[nb][0] * scale);
                float p1 = __expf(acc[nb][1] * scale);
                float p2 = __expf(acc[nb][2] * scale);
                float p3 = __expf(acc[nb][3] * scale);
                if (need_mask) {
                    if (colg     > r0g) p0 = 0.f;
                    if (colg + 1 > r0g) p1 = 0.f;
                    if (colg     > r1g) p2 = 0.f;
                    if (colg + 1 > r1g) p3 = 0.f;
                }
                ls[0] += p0 + p1; ls[1] += p2 + p3;
                int rw0 = wq + gq, rw1 = rw0 + 8;
                int c = wk*4 + nb;
                uint32_t o0b = swz128(rw0, c) + tig*4;
                uint32_t o1b = swz128(rw1, c) + tig*4;
                *reinterpret_cast<__half2*>(pL + o0b) =
                    __half2(__float2half(p0), __float2half(p1));
                *reinterpret_cast<__half2*>(pL + o1b) =
                    __half2(__float2half(p2), __float2half(p3));
            }
        };

        qk_steps(0, 2);
        do_exp(SCALE0, lsum[0], 0);
        qk_steps(2, 4);
        do_exp(SCALE1, lsum[1], 1);
        qk_steps(4, 8);
        do_exp(SCALE2, lsum[2], 2);
        bar_pair(barid);

        // fused PV across all 3 levels (closing pair barrier is subsumed by the
        // full __syncthreads at the top of the next iteration)
        #pragma unroll
        for (int kk2 = 0; kk2 < 4; kk2++) {
            uint32_t poff = prow_off + (uint32_t)(((kk2*2 + (mat>>1)) ^ qsw) << 4);
            uint32_t p0f[4], p1f[4], p2f[4];
            ldsm4(p0f, sb + P_OFF + poff);
            ldsm4(p1f, sb + P_OFF + PTILE + poff);
            ldsm4(p2f, sb + P_OFF + 2*PTILE + poff);
            {
                int rv = wk*16 + (mat >> 1)*8 + rin;
                uint32_t r4[4];
                ldsm4(r4, vst + swz128(rv, kk2*2 + (mat & 1)));
                uint32_t v0[2] = {r4[0], r4[1]}, v1[2] = {r4[2], r4[3]};
                mma16816(o0[0], p0f, v0);
                mma16816(o0[1], p0f, v1);
            }
            {
                int rv = 32 + wk*16 + (mat >> 1)*8 + rin;
                uint32_t r4[4];
                ldsm4(r4, vst + swz128(rv, kk2*2 + (mat & 1)));
                uint32_t v0[2] = {r4[0], r4[1]}, v1[2] = {r4[2], r4[3]};
                mma16816(o1[0], p1f, v0);
                mma16816(o1[1], p1f, v1);
            }
            #pragma unroll
            for (int nb2 = 0; nb2 < 2; nb2++) {
                int rv = 64 + wk*32 + nb2*16 + (mat >> 1)*8 + rin;
                uint32_t r4[4];
                ldsm4(r4, vst + swz128(rv, kk2*2 + (mat & 1)));
                uint32_t v0[2] = {r4[0], r4[1]}, v1[2] = {r4[2], r4[3]};
                mma16816(o2[2*nb2],   p2f, v0);
                mma16816(o2[2*nb2+1], p2f, v1);
            }
        }
    }
    __syncthreads();   // protect P region before lred aliasing below

    #pragma unroll
    for (int L = 0; L < 3; L++)
        #pragma unroll
        for (int j = 0; j < 2; j++) {
            lsum[L][j] += __shfl_xor_sync(0xffffffffu, lsum[L][j], 1);
            lsum[L][j] += __shfl_xor_sync(0xffffffffu, lsum[L][j], 2);
        }
    if (tig == 0) {
        #pragma unroll
        for (int L = 0; L < 3; L++) {
            lred[L*256 + (wq + gq)*2 + wk]     = lsum[L][0];
            lred[L*256 + (wq + gq + 8)*2 + wk] = lsum[L][1];
        }
    }
    __syncthreads();

    const int r0 = wq + gq, r1 = r0 + 8;

    if (wk == 0 && tig == 0) {
        int idx0 = (b*H_ + h)*S_ + q0 + r0;
        int idx1 = idx0 + 8;
        #pragma unroll
        for (int L = 0; L < 3; L++) {
            g_lsum[(zz*3 + L)*BHS_ + idx0] = lred[L*256 + r0*2] + lred[L*256 + r0*2 + 1];
            g_lsum[(zz*3 + L)*BHS_ + idx1] = lred[L*256 + r1*2] + lred[L*256 + r1*2 + 1];
        }
    }

    float* part = g_part + (size_t)zz * PZ_;
    size_t base0 = ((size_t)(b*S_ + q0 + r0)) * D_ + (size_t)h * DH_;
    size_t base1 = ((size_t)(b*S_ + q0 + r1)) * D_ + (size_t)h * DH_;
    #pragma unroll
    for (int j = 0; j < 2; j++) {
        int d = wk*16 + j*8 + tig*2;
        *reinterpret_cast<float2*>(part + base0 + d)      = make_float2(o0[j][0], o0[j][1]);
        *reinterpret_cast<float2*>(part + base1 + d)      = make_float2(o0[j][2], o0[j][3]);
        *reinterpret_cast<float2*>(part + base0 + 32 + d) = make_float2(o1[j][0], o1[j][1]);
        *reinterpret_cast<float2*>(part + base1 + 32 + d) = make_float2(o1[j][2], o1[j][3]);
    }
    #pragma unroll
    for (int j = 0; j < 4; j++) {
        int d = 64 + wk*32 + j*8 + tig*2;
        *reinterpret_cast<float2*>(part + base0 + d) = make_float2(o2[j][0], o2[j][1]);
        *reinterpret_cast<float2*>(part + base1 + d) = make_float2(o2[j][2], o2[j][3]);
    }
}

// ================= attention combine =================
__global__ __launch_bounds__(256)
void attn_combine()
{
    const int m = blockIdx.x;
    const int col = blockIdx.y * 512 + threadIdx.x * 2;
    float2 p0 = *reinterpret_cast<const float2*>(g_part + (size_t)m*D_ + col);
    float2 p1 = *reinterpret_cast<const float2*>(g_part + PZ_ + (size_t)m*D_ + col);
    const int h = col >> 7, d = col & 127;
    const int L = (d < 32) ? 0 : (d < 64) ? 1 : 2;
    const int b = m >> 10, s = m & 1023;
    const int idx = (b*H_ + h)*S_ + s;
    float ls = g_lsum[L*BHS_ + idx] + g_lsum[(3 + L)*BHS_ + idx];
    float inv = 1.f / ls;
    size_t o = (size_t)m * D_ + col;
    *reinterpret_cast<__half2*>(g_AO + o) =
        __half2(__float2half((p0.x + p1.x) * inv), __float2half((p0.y + p1.y) * inv));
}

// ================= launch =================
extern "C" void kernel_launch(void* const* d_in, const int* in_sizes, int n_in,
                              void* d_out, int out_size)
{
    (void)in_sizes; (void)n_in; (void)out_size;
    const float* x  = (const float*)d_in[0];
    const float* Wq = (const float*)d_in[2];
    const float* bq = (const float*)d_in[3];
    const float* Wk = (const float*)d_in[4];
    const float* bk = (const float*)d_in[5];
    const float* Wv = (const float*)d_in[6];
    const float* bv = (const float*)d_in[7];
    const float* Wo = (const float*)d_in[8];
    const float* bo = (const float*)d_in[9];
    float* out = (float*)d_out;

    // merged converter: z=0 convx (8192,1), z=1 Wqkv (48,32), z=2 Wo (32,32)
    conv_all_kernel<<<dim3(8192, 32, 3), 256>>>(x, Wq, Wk, Wv, Wo);

    static __half *px = nullptr, *pwt, *pwot, *pao;
    if (!px) {
        cudaGetSymbolAddress((void**)&px, g_x);
        cudaGetSymbolAddress((void**)&pwt, g_Wt);
        cudaGetSymbolAddress((void**)&pwot, g_Wot);
        cudaGetSymbolAddress((void**)&pao, g_AO);
    }

    static bool attr_set = false;
    if (!attr_set) {
        cudaFuncSetAttribute(gemm_mma_kernel<0>, cudaFuncAttributeMaxDynamicSharedMemorySize, GEMM_SMEM);
        cudaFuncSetAttribute(gemm_mma_kernel<1>, cudaFuncAttributeMaxDynamicSharedMemorySize, GEMM_SMEM);
        cudaFuncSetAttribute(attn_mma_kernel, cudaFuncAttributeMaxDynamicSharedMemorySize, ATT_SMEM);
        attr_set = true;
    }

    gemm_mma_kernel<0><<<dim3(NTOT_/128, MROWS_/128), 256, GEMM_SMEM>>>(
        px, pwt, nullptr, bq, bk, bv);

    attn_mma_kernel<<<dim3(S_/QT, H_, B_*2), 512, ATT_SMEM>>>();
    attn_combine<<<dim3(MROWS_, 4), 256>>>();

    gemm_mma_kernel<1><<<dim3(D_/128, MROWS_/128), 256, GEMM_SMEM>>>(
        pao, pwot, out, bo, nullptr, nullptr);
}